// round 2
// baseline (speedup 1.0000x reference)
#include <cuda_runtime.h>
#include <math.h>

// Problem constants
#define Bc 256
#define Tc 8
#define Sc 200
#define Rc 8
#define Dc 64
#define Fc 20

#define SEQ_ST 68    // seq row stride in floats (float4-aligned, bank-skewed)
#define ATT_ST 201   // att/decay row stride ([R][201]) -> conflict-free patterns

#define SMEM_FLOATS (Sc*SEQ_ST + Rc*SEQ_ST + 2*Rc*ATT_ST + 2*Rc*Fc + Sc)
#define SMEM_BYTES  (SMEM_FLOATS*4)

__global__ __launch_bounds__(256, 3)
void rda_kernel(const float* __restrict__ seq,
                const float* __restrict__ delta,
                const float* __restrict__ target,
                const float* __restrict__ tv,
                const int*   __restrict__ valid,
                const float* __restrict__ rel,
                const float* __restrict__ fr,
                const float* __restrict__ fi,
                float* __restrict__ out)
{
    extern __shared__ float sm[];
    float* s_seq = sm;                       // [S][SEQ_ST]
    float* s_ri  = s_seq + Sc*SEQ_ST;        // [R][SEQ_ST]
    float* s_att = s_ri  + Rc*SEQ_ST;        // [R][ATT_ST]
    float* s_dec = s_att + Rc*ATT_ST;        // [R][ATT_ST]
    float* s_fr  = s_dec + Rc*ATT_ST;        // [R][F]
    float* s_fi  = s_fr  + Rc*Fc;            // [R][F]
    float* s_val = s_fi  + Rc*Fc;            // [S] (1.0 valid / 0.0 invalid)

    const int tid = threadIdx.x;
    const int t = blockIdx.x;
    const int b = blockIdx.y;

    // ---------------- Load phase ----------------
    // seq[b] : 200x64 floats -> smem (stride 68)
    {
        const float4* g = (const float4*)(seq + (size_t)b * Sc * Dc);
        for (int i = tid; i < Sc * (Dc/4); i += 256) {
            int s = i >> 4, d4 = i & 15;            // Dc/4 == 16
            ((float4*)(s_seq + s*SEQ_ST))[d4] = g[s*16 + d4];
        }
    }
    // ri[r][d] = (rel[r][d] + tv[b,t,r,d]) * target[b,t,d]
    {
        const float4* gtv = (const float4*)(tv + (size_t)(b*Tc + t) * Rc * Dc);
        const float4* gtg = (const float4*)(target + (size_t)(b*Tc + t) * Dc);
        const float4* grl = (const float4*)rel;
        for (int i = tid; i < Rc * (Dc/4); i += 256) {
            int r = i >> 4, d4 = i & 15;
            float4 e = grl[r*16 + d4];
            float4 v = gtv[r*16 + d4];
            float4 g = gtg[d4];
            float4 o;
            o.x = (e.x + v.x) * g.x;
            o.y = (e.y + v.y) * g.y;
            o.z = (e.z + v.z) * g.z;
            o.w = (e.w + v.w) * g.w;
            ((float4*)(s_ri + r*SEQ_ST))[d4] = o;
        }
    }
    for (int i = tid; i < Rc*Fc; i += 256) { s_fr[i] = fr[i]; s_fi[i] = fi[i]; }
    __syncthreads();

    // ---------------- Decay (IDFT, folded symmetry) + valid flags ----------------
    // decay[s][r] = clip( (1/(2F)) * sum_f cos(pi*f/(F-1)*dt)*fr[r][f] - sin(..)*fi[r][f], 0, 1 )
    if (tid < Sc) {
        float dt = delta[b*Sc + tid];
        int   v  = valid[b*Sc + tid];
        s_val[tid] = v ? 1.0f : 0.0f;
        float acc[Rc];
        #pragma unroll
        for (int r = 0; r < Rc; r++) acc[r] = 0.0f;
        #pragma unroll
        for (int f = 0; f < Fc; f++) {
            float w = 3.14159265358979323846f * ((float)f * (1.0f/(Fc-1))) * dt;
            float sn, cs;
            __sincosf(w, &sn, &cs);
            #pragma unroll
            for (int r = 0; r < Rc; r++)
                acc[r] = fmaf(cs, s_fr[r*Fc + f], fmaf(-sn, s_fi[r*Fc + f], acc[r]));
        }
        #pragma unroll
        for (int r = 0; r < Rc; r++) {
            float d = acc[r] * (1.0f / (2.0f * Fc));
            d = fminf(fmaxf(d, 0.0f), 1.0f);
            if (!v) d = 0.0f;
            s_dec[r*ATT_ST + tid] = d;
        }
    }

    // ---------------- Attention logits: att[s][r] = dot(seq[s], ri[r]) over D ----------------
    for (int idx = tid; idx < Sc*Rc; idx += 256) {
        int s = idx >> 3, r = idx & 7;
        const float4* a = (const float4*)(s_seq + s*SEQ_ST);
        const float4* q = (const float4*)(s_ri  + r*SEQ_ST);
        float acc = 0.0f;
        #pragma unroll
        for (int j = 0; j < 16; j++) {
            float4 x = a[j], y = q[j];
            acc = fmaf(x.x, y.x, acc);
            acc = fmaf(x.y, y.y, acc);
            acc = fmaf(x.z, y.z, acc);
            acc = fmaf(x.w, y.w, acc);
        }
        s_att[r*ATT_ST + s] = acc;
    }
    __syncthreads();

    // ---------------- Masked softmax over S (per warp: r = warp), then * decay ----------------
    const int warp = tid >> 5;
    const int lane = tid & 31;
    {
        float* arow = s_att + warp*ATT_ST;
        const float* drow = s_dec + warp*ATT_ST;

        float mx = -INFINITY;
        for (int s = lane; s < Sc; s += 32)
            if (s_val[s] != 0.0f) mx = fmaxf(mx, arow[s]);
        #pragma unroll
        for (int o = 16; o; o >>= 1) mx = fmaxf(mx, __shfl_xor_sync(0xffffffffu, mx, o));

        float sum = 0.0f;
        for (int s = lane; s < Sc; s += 32) {
            float e = (s_val[s] != 0.0f) ? __expf(arow[s] - mx) : 0.0f;
            arow[s] = e;
            sum += e;
        }
        #pragma unroll
        for (int o = 16; o; o >>= 1) sum += __shfl_xor_sync(0xffffffffu, sum, o);

        float inv = 1.0f / sum;
        for (int s = lane; s < Sc; s += 32)
            arow[s] = arow[s] * inv * drow[s];
    }
    __syncthreads();

    // ---------------- Context: out[r][d] = sum_s seq[s][d] * w[s][r] ----------------
    {
        const float* wrow = s_att + warp*ATT_ST;   // weights for r = warp
        const int d0 = lane * 2;
        float2 acc = make_float2(0.0f, 0.0f);
        #pragma unroll 4
        for (int s = 0; s < Sc; s++) {
            float w = wrow[s];                               // broadcast
            float2 q = *(const float2*)(s_seq + s*SEQ_ST + d0);
            acc.x = fmaf(q.x, w, acc.x);
            acc.y = fmaf(q.y, w, acc.y);
        }
        float2* go = (float2*)(out + (((size_t)(b*Tc + t))*Rc + warp) * Dc);
        go[lane] = acc;
    }
}

extern "C" void kernel_launch(void* const* d_in, const int* in_sizes, int n_in,
                              void* d_out, int out_size)
{
    const float* seq    = (const float*)d_in[0];
    const float* delta  = (const float*)d_in[1];
    const float* target = (const float*)d_in[2];
    const float* tv     = (const float*)d_in[3];
    const int*   valid  = (const int*)  d_in[4];
    const float* rel    = (const float*)d_in[5];
    const float* fr     = (const float*)d_in[6];
    const float* fi     = (const float*)d_in[7];
    float* out = (float*)d_out;

    cudaFuncSetAttribute(rda_kernel, cudaFuncAttributeMaxDynamicSharedMemorySize, SMEM_BYTES);
    dim3 grid(Tc, Bc);
    rda_kernel<<<grid, 256, SMEM_BYTES>>>(seq, delta, target, tv, valid, rel, fr, fi, out);
}

// round 3
// speedup vs baseline: 1.1888x; 1.1888x over previous
#include <cuda_runtime.h>
#include <math.h>

// Problem constants
#define Bc 256
#define Tc 8
#define Sc 200
#define Rc 8
#define Dc 64
#define Fc 20

#define SEQ_ST 68    // seq row stride (float4-aligned; 68 mod 32 = 4 -> 4-phase LDS.128 row-per-lane)
#define ATT_ST 201   // att/dec row stride
#define WST    8     // transposed weight stride [S][8]

// SMEM layout (floats)
#define OFF_SEQ  0
#define OFF_RI   (OFF_SEQ + Sc*SEQ_ST)            // 13600
#define OFF_ATT  (OFF_RI  + Rc*SEQ_ST)            // +544
#define OFF_DEC  (OFF_ATT + Rc*ATT_ST)            // +1608
#define OFF_W    (OFF_DEC + Rc*ATT_ST)            // +1608
#define OFF_FR   (OFF_W   + Sc*WST)               // +1600
#define OFF_FI   (OFF_FR  + Rc*Fc)
#define OFF_VAL  (OFF_FI  + Rc*Fc)
#define SMEM_FLOATS (OFF_VAL + Sc)
#define SMEM_BYTES  (SMEM_FLOATS*4)
// partials alias the dead att+dec region (3216 floats >= 2048 needed)
#define OFF_PART OFF_ATT

__device__ __forceinline__ unsigned long long fma2(unsigned long long a,
                                                   unsigned long long b,
                                                   unsigned long long c) {
    unsigned long long d;
    asm("fma.rn.f32x2 %0, %1, %2, %3;" : "=l"(d) : "l"(a), "l"(b), "l"(c));
    return d;
}
__device__ __forceinline__ float2 unpack2(unsigned long long v) {
    float2 f;
    asm("mov.b64 {%0,%1}, %2;" : "=f"(f.x), "=f"(f.y) : "l"(v));
    return f;
}

__global__ __launch_bounds__(256, 2)
void rda_kernel(const float* __restrict__ seq,
                const float* __restrict__ delta,
                const float* __restrict__ target,
                const float* __restrict__ tv,
                const int*   __restrict__ valid,
                const float* __restrict__ rel,
                const float* __restrict__ fr,
                const float* __restrict__ fi,
                float* __restrict__ out)
{
    extern __shared__ float sm[];
    float* s_seq = sm + OFF_SEQ;
    float* s_ri  = sm + OFF_RI;
    float* s_att = sm + OFF_ATT;
    float* s_dec = sm + OFF_DEC;
    float* s_w   = sm + OFF_W;
    float* s_fr  = sm + OFF_FR;
    float* s_fi  = sm + OFF_FI;
    float* s_val = sm + OFF_VAL;
    float* s_part = sm + OFF_PART;   // alias (att+dec), used in context phase only

    const int tid = threadIdx.x;
    const int t = blockIdx.x;
    const int b = blockIdx.y;

    // ---------------- Load phase ----------------
    {
        const float4* g = (const float4*)(seq + (size_t)b * Sc * Dc);
        for (int i = tid; i < Sc * (Dc/4); i += 256) {
            int s = i >> 4, d4 = i & 15;
            ((float4*)(s_seq + s*SEQ_ST))[d4] = g[s*16 + d4];
        }
    }
    {
        const float4* gtv = (const float4*)(tv + (size_t)(b*Tc + t) * Rc * Dc);
        const float4* gtg = (const float4*)(target + (size_t)(b*Tc + t) * Dc);
        const float4* grl = (const float4*)rel;
        for (int i = tid; i < Rc * (Dc/4); i += 256) {
            int r = i >> 4, d4 = i & 15;
            float4 e = grl[r*16 + d4];
            float4 v = gtv[r*16 + d4];
            float4 g = gtg[d4];
            float4 o;
            o.x = (e.x + v.x) * g.x;
            o.y = (e.y + v.y) * g.y;
            o.z = (e.z + v.z) * g.z;
            o.w = (e.w + v.w) * g.w;
            ((float4*)(s_ri + r*SEQ_ST))[d4] = o;
        }
    }
    for (int i = tid; i < Rc*Fc; i += 256) { s_fr[i] = fr[i]; s_fi[i] = fi[i]; }
    __syncthreads();

    // ---------------- Decay (folded IDFT symmetry) + valid flags ----------------
    if (tid < Sc) {
        float dt = delta[b*Sc + tid];
        int   v  = valid[b*Sc + tid];
        s_val[tid] = v ? 1.0f : 0.0f;
        float acc[Rc];
        #pragma unroll
        for (int r = 0; r < Rc; r++) acc[r] = 0.0f;
        #pragma unroll
        for (int f = 0; f < Fc; f++) {
            float w = 3.14159265358979323846f * ((float)f * (1.0f/(Fc-1))) * dt;
            float sn, cs;
            __sincosf(w, &sn, &cs);
            #pragma unroll
            for (int r = 0; r < Rc; r++)
                acc[r] = fmaf(cs, s_fr[r*Fc + f], fmaf(-sn, s_fi[r*Fc + f], acc[r]));
        }
        #pragma unroll
        for (int r = 0; r < Rc; r++) {
            float d = acc[r] * (1.0f / (2.0f * Fc));
            d = fminf(fmaxf(d, 0.0f), 1.0f);
            if (!v) d = 0.0f;
            s_dec[r*ATT_ST + tid] = d;
        }
    }

    // ---------------- att[s][r] = dot(seq[s], ri[r]); thread-per-s, 8 r-accs ----------------
    if (tid < Sc) {
        const int s = tid;
        const ulonglong2* a = (const ulonglong2*)(s_seq + s*SEQ_ST);
        unsigned long long alo[Rc], ahi[Rc];
        #pragma unroll
        for (int r = 0; r < Rc; r++) { alo[r] = 0ull; ahi[r] = 0ull; }
        #pragma unroll
        for (int d4 = 0; d4 < 16; d4++) {
            ulonglong2 x = a[d4];
            #pragma unroll
            for (int r = 0; r < Rc; r++) {
                ulonglong2 y = ((const ulonglong2*)(s_ri + r*SEQ_ST))[d4];  // broadcast
                alo[r] = fma2(x.x, y.x, alo[r]);
                ahi[r] = fma2(x.y, y.y, ahi[r]);
            }
        }
        #pragma unroll
        for (int r = 0; r < Rc; r++) {
            float2 u = unpack2(alo[r]);
            float2 v = unpack2(ahi[r]);
            s_att[r*ATT_ST + s] = (u.x + u.y) + (v.x + v.y);
        }
    }
    __syncthreads();

    // ---------------- Masked softmax over S (warp r), write weights transposed [S][8] ----------------
    const int warp = tid >> 5;
    const int lane = tid & 31;
    {
        const float* arow = s_att + warp*ATT_ST;
        const float* drow = s_dec + warp*ATT_ST;

        float mx = -INFINITY;
        for (int s = lane; s < Sc; s += 32)
            if (s_val[s] != 0.0f) mx = fmaxf(mx, arow[s]);
        #pragma unroll
        for (int o = 16; o; o >>= 1) mx = fmaxf(mx, __shfl_xor_sync(0xffffffffu, mx, o));

        float sum = 0.0f;
        float ev[7];                         // 200/32 -> up to 7 per lane
        int n = 0;
        for (int s = lane; s < Sc; s += 32) {
            float e = (s_val[s] != 0.0f) ? __expf(arow[s] - mx) : 0.0f;
            ev[n++] = e;
            sum += e;
        }
        #pragma unroll
        for (int o = 16; o; o >>= 1) sum += __shfl_xor_sync(0xffffffffu, sum, o);

        float inv = 1.0f / sum;
        n = 0;
        for (int s = lane; s < Sc; s += 32)
            s_w[s*WST + warp] = ev[n++] * inv * drow[s];
    }
    __syncthreads();

    // ---------------- Context: out[r][d] = sum_s seq[s][d]*w[s][r] ----------------
    // warp -> (r-group rg = warp&1 -> r in [rg*4, rg*4+4), s-chunk c = warp>>1 -> 50 s)
    {
        const int rg = warp & 1;
        const int c  = warp >> 1;
        const int s0 = c * 50;
        const int d0 = lane * 2;
        float ax[4], ay[4];
        #pragma unroll
        for (int j = 0; j < 4; j++) { ax[j] = 0.0f; ay[j] = 0.0f; }
        #pragma unroll 2
        for (int s = s0; s < s0 + 50; s++) {
            float4 wv = *(const float4*)(s_w + s*WST + rg*4);      // broadcast
            float2 q  = *(const float2*)(s_seq + s*SEQ_ST + d0);
            ax[0] = fmaf(q.x, wv.x, ax[0]);  ay[0] = fmaf(q.y, wv.x, ay[0]);
            ax[1] = fmaf(q.x, wv.y, ax[1]);  ay[1] = fmaf(q.y, wv.y, ay[1]);
            ax[2] = fmaf(q.x, wv.z, ax[2]);  ay[2] = fmaf(q.y, wv.z, ay[2]);
            ax[3] = fmaf(q.x, wv.w, ax[3]);  ay[3] = fmaf(q.y, wv.w, ay[3]);
        }
        // partials: block (c*2+rg), layout [j*64 + d]
        float* p = s_part + (c*2 + rg) * 256;
        #pragma unroll
        for (int j = 0; j < 4; j++)
            *(float2*)(p + j*64 + d0) = make_float2(ax[j], ay[j]);
    }
    __syncthreads();

    // reduce 4 chunks, write out
    {
        const int rg = tid >> 7;             // 0..1
        const int j  = (tid >> 5) & 3;       // 0..3
        const int d0 = lane * 2;
        float2 acc = make_float2(0.0f, 0.0f);
        #pragma unroll
        for (int c = 0; c < 4; c++) {
            float2 v = *(const float2*)(s_part + (c*2 + rg)*256 + j*64 + d0);
            acc.x += v.x; acc.y += v.y;
        }
        const int r = rg*4 + j;
        float2* go = (float2*)(out + (((size_t)(b*Tc + t))*Rc + r) * Dc + d0);
        *go = acc;
    }
}

extern "C" void kernel_launch(void* const* d_in, const int* in_sizes, int n_in,
                              void* d_out, int out_size)
{
    const float* seq    = (const float*)d_in[0];
    const float* delta  = (const float*)d_in[1];
    const float* target = (const float*)d_in[2];
    const float* tv     = (const float*)d_in[3];
    const int*   valid  = (const int*)  d_in[4];
    const float* rel    = (const float*)d_in[5];
    const float* fr     = (const float*)d_in[6];
    const float* fi     = (const float*)d_in[7];
    float* out = (float*)d_out;

    cudaFuncSetAttribute(rda_kernel, cudaFuncAttributeMaxDynamicSharedMemorySize, SMEM_BYTES);
    dim3 grid(Tc, Bc);
    rda_kernel<<<grid, 256, SMEM_BYTES>>>(seq, delta, target, tv, valid, fr ? rel : rel, fr, fi, out);
}

// round 4
// speedup vs baseline: 1.6147x; 1.3583x over previous
#include <cuda_runtime.h>
#include <math.h>

// Problem constants
#define Bc 256
#define Tc 8
#define Sc 200
#define Rc 8
#define Dc 64
#define Fc 20
#define TPC 4            // t-values per CTA
#define NT 512           // threads per CTA

#define SEQ_ST 68        // seq row stride (float4-aligned, conflict-free LDS.128)
#define WST 12           // att/w row stride per (t,s): 48B -> float4-aligned
#define DEC_ST 201

// SMEM layout (floats)
#define OFF_SEQ 0
#define OFF_RI  (Sc*SEQ_ST)                    // 13600
#define OFF_ATT (OFF_RI + TPC*Rc*SEQ_ST)       // 15776
#define OFF_DEC (OFF_ATT + TPC*Sc*WST)         // 25376
#define OFF_FR  (OFF_DEC + Rc*DEC_ST)          // 26984
#define OFF_FI  (OFF_FR + Rc*Fc)               // 27144
#define OFF_VAL (OFF_FI + Rc*Fc)               // 27304
#define SMEM_FLOATS (OFF_VAL + Sc + 24)        // 27528
#define SMEM_BYTES  (SMEM_FLOATS*4)            // ~110KB -> 2 CTAs/SM
// context partials (2048 floats) alias dec+fr+fi+val (2152 floats, dead by then)
#define OFF_PART OFF_DEC

__global__ __launch_bounds__(NT, 2)
void rda_kernel(const float* __restrict__ seq,
                const float* __restrict__ delta,
                const float* __restrict__ target,
                const float* __restrict__ tv,
                const int*   __restrict__ valid,
                const float* __restrict__ rel,
                const float* __restrict__ fr,
                const float* __restrict__ fi,
                float* __restrict__ out)
{
    extern __shared__ float sm[];
    float* s_seq = sm + OFF_SEQ;
    float* s_ri  = sm + OFF_RI;
    float* s_att = sm + OFF_ATT;
    float* s_dec = sm + OFF_DEC;
    float* s_fr  = sm + OFF_FR;
    float* s_fi  = sm + OFF_FI;
    float* s_val = sm + OFF_VAL;
    float* s_part = sm + OFF_PART;

    const int tid  = threadIdx.x;
    const int lane = tid & 31;
    const int warp = tid >> 5;
    const int t0 = blockIdx.x * TPC;
    const int b  = blockIdx.y;

    // ---------------- Load phase ----------------
    {
        const float4* g = (const float4*)(seq + (size_t)b * Sc * Dc);
        #pragma unroll
        for (int i = tid; i < Sc * (Dc/4); i += NT) {
            int s = i >> 4, d4 = i & 15;
            ((float4*)(s_seq + s*SEQ_ST))[d4] = g[s*16 + d4];
        }
    }
    {
        // ri[t][r][d] = (rel[r][d] + tv[b,t0+t,r,d]) * target[b,t0+t,d]   (exactly 1 float4/thread)
        int i = tid;                     // i < TPC*Rc*16 == 512 == NT
        int tr = i >> 4;                 // 0..31
        int t = tr >> 3, r = tr & 7, d4 = i & 15;
        float4 e = ((const float4*)rel)[r*16 + d4];
        float4 v = ((const float4*)tv)[((size_t)(b*Tc + t0 + t)*Rc + r)*16 + d4];
        float4 g = ((const float4*)target)[(size_t)(b*Tc + t0 + t)*16 + d4];
        float4 o;
        o.x = (e.x + v.x) * g.x;
        o.y = (e.y + v.y) * g.y;
        o.z = (e.z + v.z) * g.z;
        o.w = (e.w + v.w) * g.w;
        ((float4*)(s_ri + tr*SEQ_ST))[d4] = o;
    }
    if (tid < Rc*Fc) { s_fr[tid] = fr[tid]; s_fi[tid] = fi[tid]; }
    __syncthreads();

    // ---------------- att units + decay (independent; no barrier between) ----------------
    // att unit u in [0,800): t=u/200, s=u%200; dot(seq[s], ri[t][r]) over D for 8 r's
    {
        int u = tid;
        {
            int t = u / Sc;
            int s = u - t*Sc;
            const float4* a = (const float4*)(s_seq + s*SEQ_ST);
            const float*  rib = s_ri + t*Rc*SEQ_ST;
            float acc[Rc];
            #pragma unroll
            for (int r = 0; r < Rc; r++) acc[r] = 0.0f;
            #pragma unroll
            for (int d4 = 0; d4 < 16; d4++) {
                float4 x = a[d4];
                #pragma unroll
                for (int r = 0; r < Rc; r++) {
                    float4 y = ((const float4*)(rib + r*SEQ_ST))[d4];   // broadcast
                    acc[r] = fmaf(x.x, y.x, acc[r]);
                    acc[r] = fmaf(x.y, y.y, acc[r]);
                    acc[r] = fmaf(x.z, y.z, acc[r]);
                    acc[r] = fmaf(x.w, y.w, acc[r]);
                }
            }
            float* w = s_att + (t*Sc + s)*WST;
            ((float4*)w)[0] = make_float4(acc[0], acc[1], acc[2], acc[3]);
            ((float4*)w)[1] = make_float4(acc[4], acc[5], acc[6], acc[7]);
        }

        // decay for s = tid-312 (threads 312..511), fused here to hide MUFU latency
        if (tid >= 312) {
            int s = tid - 312;
            float dt = delta[b*Sc + s];
            int   v  = valid[b*Sc + s];
            s_val[s] = v ? 1.0f : 0.0f;
            float acc[Rc];
            #pragma unroll
            for (int r = 0; r < Rc; r++) acc[r] = 0.0f;
            #pragma unroll
            for (int f = 0; f < Fc; f++) {
                float w = 3.14159265358979323846f * ((float)f * (1.0f/(Fc-1))) * dt;
                float sn, cs;
                __sincosf(w, &sn, &cs);
                #pragma unroll
                for (int r = 0; r < Rc; r++)
                    acc[r] = fmaf(cs, s_fr[r*Fc + f], fmaf(-sn, s_fi[r*Fc + f], acc[r]));
            }
            #pragma unroll
            for (int r = 0; r < Rc; r++) {
                float d = acc[r] * (1.0f / (2.0f * Fc));
                d = fminf(fmaxf(d, 0.0f), 1.0f);
                if (!v) d = 0.0f;
                s_dec[r*DEC_ST + s] = d;
            }
        }

        // second att unit for tid < 288 (units 512..799)
        u = tid + NT;
        if (u < TPC*Sc) {
            int t = u / Sc;
            int s = u - t*Sc;
            const float4* a = (const float4*)(s_seq + s*SEQ_ST);
            const float*  rib = s_ri + t*Rc*SEQ_ST;
            float acc[Rc];
            #pragma unroll
            for (int r = 0; r < Rc; r++) acc[r] = 0.0f;
            #pragma unroll
            for (int d4 = 0; d4 < 16; d4++) {
                float4 x = a[d4];
                #pragma unroll
                for (int r = 0; r < Rc; r++) {
                    float4 y = ((const float4*)(rib + r*SEQ_ST))[d4];
                    acc[r] = fmaf(x.x, y.x, acc[r]);
                    acc[r] = fmaf(x.y, y.y, acc[r]);
                    acc[r] = fmaf(x.z, y.z, acc[r]);
                    acc[r] = fmaf(x.w, y.w, acc[r]);
                }
            }
            float* w = s_att + (t*Sc + s)*WST;
            ((float4*)w)[0] = make_float4(acc[0], acc[1], acc[2], acc[3]);
            ((float4*)w)[1] = make_float4(acc[4], acc[5], acc[6], acc[7]);
        }
    }
    __syncthreads();

    // ---------------- Masked softmax over S, in-place, * decay ----------------
    // 32 rows (t,r); warp handles rows 2*warp, 2*warp+1
    {
        #pragma unroll
        for (int i = 0; i < 2; i++) {
            int row = warp*2 + i;
            int t = row >> 3, r = row & 7;
            float* arow = s_att + t*Sc*WST + r;         // element s at arow[s*WST]
            const float* drow = s_dec + r*DEC_ST;

            float mx = -INFINITY;
            for (int s = lane; s < Sc; s += 32)
                if (s_val[s] != 0.0f) mx = fmaxf(mx, arow[s*WST]);
            #pragma unroll
            for (int o = 16; o; o >>= 1) mx = fmaxf(mx, __shfl_xor_sync(0xffffffffu, mx, o));

            float sum = 0.0f;
            float ev[7];
            int n = 0;
            for (int s = lane; s < Sc; s += 32) {
                float e = (s_val[s] != 0.0f) ? __expf(arow[s*WST] - mx) : 0.0f;
                ev[n++] = e;
                sum += e;
            }
            #pragma unroll
            for (int o = 16; o; o >>= 1) sum += __shfl_xor_sync(0xffffffffu, sum, o);

            float inv = 1.0f / sum;
            n = 0;
            for (int s = lane; s < Sc; s += 32)
                arow[s*WST] = ev[n++] * inv * drow[s];
        }
    }
    __syncthreads();

    // ---------------- Context: out[t][r][d] = sum_s seq[s][d] * w[t][s][r] ----------------
    // warp -> (t = warp>>2, rg = (warp>>1)&1, sh = warp&1); 100 s per warp
    {
        const int t  = warp >> 2;
        const int rg = (warp >> 1) & 1;
        const int sh = warp & 1;
        const int s0 = sh * 100;
        const int d0 = lane * 2;
        const float* wbase = s_att + t*Sc*WST + rg*4;
        float ax[4], ay[4];
        #pragma unroll
        for (int j = 0; j < 4; j++) { ax[j] = 0.0f; ay[j] = 0.0f; }
        #pragma unroll 2
        for (int s = s0; s < s0 + 100; s++) {
            float4 wv = *(const float4*)(wbase + s*WST);           // broadcast
            float2 q  = *(const float2*)(s_seq + s*SEQ_ST + d0);
            ax[0] = fmaf(q.x, wv.x, ax[0]);  ay[0] = fmaf(q.y, wv.x, ay[0]);
            ax[1] = fmaf(q.x, wv.y, ax[1]);  ay[1] = fmaf(q.y, wv.y, ay[1]);
            ax[2] = fmaf(q.x, wv.z, ax[2]);  ay[2] = fmaf(q.y, wv.z, ay[2]);
            ax[3] = fmaf(q.x, wv.w, ax[3]);  ay[3] = fmaf(q.y, wv.w, ay[3]);
        }

        // sh==1 warps publish partials (aliased over dead dec/fr/fi/val)
        if (sh == 1) {
            float* p = s_part + (t*2 + rg) * 256;
            #pragma unroll
            for (int j = 0; j < 4; j++)
                *(float2*)(p + j*64 + d0) = make_float2(ax[j], ay[j]);
        }
        __syncthreads();

        if (sh == 0) {
            const float* p = s_part + (t*2 + rg) * 256;
            #pragma unroll
            for (int j = 0; j < 4; j++) {
                float2 v = *(const float2*)(p + j*64 + d0);
                float2 res = make_float2(ax[j] + v.x, ay[j] + v.y);
                float2* go = (float2*)(out + (((size_t)(b*Tc + t0 + t))*Rc + rg*4 + j)*Dc + d0);
                *go = res;
            }
        }
    }
}

extern "C" void kernel_launch(void* const* d_in, const int* in_sizes, int n_in,
                              void* d_out, int out_size)
{
    const float* seq    = (const float*)d_in[0];
    const float* delta  = (const float*)d_in[1];
    const float* target = (const float*)d_in[2];
    const float* tv     = (const float*)d_in[3];
    const int*   valid  = (const int*)  d_in[4];
    const float* rel    = (const float*)d_in[5];
    const float* fr     = (const float*)d_in[6];
    const float* fi     = (const float*)d_in[7];
    float* out = (float*)d_out;

    cudaFuncSetAttribute(rda_kernel, cudaFuncAttributeMaxDynamicSharedMemorySize, SMEM_BYTES);
    dim3 grid(Tc/TPC, Bc);
    rda_kernel<<<grid, NT, SMEM_BYTES>>>(seq, delta, target, tv, valid, rel, fr, fi, out);
}

// round 5
// speedup vs baseline: 2.0168x; 1.2490x over previous
#include <cuda_runtime.h>
#include <math.h>

// Problem constants
#define Bc 256
#define Tc 8
#define Sc 200
#define Rc 8
#define Dc 64
#define Fc 20
#define TPC 4            // t-values per CTA
#define NT 512

#define SEQ_ST 68        // seq row stride (float4-aligned, conflict-free)
#define WST 12           // att/w row stride per (t,s)
#define DEC_ST 201

// SMEM layout (floats)
#define OFF_SEQ 0
#define OFF_RI  (Sc*SEQ_ST)                    // 13600  (2176 floats, dead after att)
#define OFF_ATT (OFF_RI + TPC*Rc*SEQ_ST)       // 15776  (9600 floats, live)
#define OFF_DEC (OFF_ATT + TPC*Sc*WST)         // 25376  (dead after softmax)
#define OFF_FR  (OFF_DEC + Rc*DEC_ST)
#define OFF_FI  (OFF_FR + Rc*Fc)
#define OFF_VAL (OFF_FI + Rc*Fc)
#define SMEM_FLOATS (OFF_VAL + Sc + 24)        // 27528 floats -> ~110KB, 2 CTAs/SM
#define SMEM_BYTES  (SMEM_FLOATS*4)
// partial-reduction scratch aliases (each needs TPC*512 = 2048 floats):
#define OFF_P1 OFF_RI     // 2176 floats available
#define OFF_P2 OFF_DEC    // 2152 floats available (dec+fr+fi+val)

typedef unsigned long long u64;

__device__ __forceinline__ u64 fma2(u64 a, u64 b, u64 c) {
    u64 d; asm("fma.rn.f32x2 %0, %1, %2, %3;" : "=l"(d) : "l"(a), "l"(b), "l"(c)); return d;
}
__device__ __forceinline__ u64 add2(u64 a, u64 b) {
    u64 d; asm("add.rn.f32x2 %0, %1, %2;" : "=l"(d) : "l"(a), "l"(b)); return d;
}
__device__ __forceinline__ u64 pack2(float lo, float hi) {
    u64 d; asm("mov.b64 %0, {%1, %2};" : "=l"(d) : "f"(lo), "f"(hi)); return d;
}

__global__ __launch_bounds__(NT, 2)
void rda_kernel(const float* __restrict__ seq,
                const float* __restrict__ delta,
                const float* __restrict__ target,
                const float* __restrict__ tv,
                const int*   __restrict__ valid,
                const float* __restrict__ rel,
                const float* __restrict__ fr,
                const float* __restrict__ fi,
                float* __restrict__ out)
{
    extern __shared__ float sm[];
    float* s_seq = sm + OFF_SEQ;
    float* s_ri  = sm + OFF_RI;
    float* s_att = sm + OFF_ATT;
    float* s_dec = sm + OFF_DEC;
    float* s_fr  = sm + OFF_FR;
    float* s_fi  = sm + OFF_FI;
    float* s_val = sm + OFF_VAL;

    const int tid  = threadIdx.x;
    const int lane = tid & 31;
    const int warp = tid >> 5;
    const int t0 = blockIdx.x * TPC;
    const int b  = blockIdx.y;

    // ---------------- Load phase ----------------
    {
        const float4* g = (const float4*)(seq + (size_t)b * Sc * Dc);
        #pragma unroll
        for (int i = tid; i < Sc * (Dc/4); i += NT) {
            int s = i >> 4, d4 = i & 15;
            ((float4*)(s_seq + s*SEQ_ST))[d4] = g[s*16 + d4];
        }
    }
    {
        // ri[t][r][d] = (rel[r][d] + tv[b,t0+t,r,d]) * target[b,t0+t,d]
        int i = tid;                     // exactly TPC*Rc*16 == 512
        int tr = i >> 4;
        int t = tr >> 3, r = tr & 7, d4 = i & 15;
        float4 e = ((const float4*)rel)[r*16 + d4];
        float4 v = ((const float4*)tv)[((size_t)(b*Tc + t0 + t)*Rc + r)*16 + d4];
        float4 g = ((const float4*)target)[(size_t)(b*Tc + t0 + t)*16 + d4];
        float4 o;
        o.x = (e.x + v.x) * g.x;
        o.y = (e.y + v.y) * g.y;
        o.z = (e.z + v.z) * g.z;
        o.w = (e.w + v.w) * g.w;
        ((float4*)(s_ri + tr*SEQ_ST))[d4] = o;
    }
    if (tid < Rc*Fc) { s_fr[tid] = fr[tid]; s_fi[tid] = fi[tid]; }
    __syncthreads();

    // ---------------- att (threads 0..399, 2 s each) + decay (threads 400..511) ----------------
    if (tid < 400) {
        int t  = tid / 100;
        int s0 = tid - t*100;            // this thread: s0 and s0+100
        const float* rib = s_ri + t*Rc*SEQ_ST;
        const float4* a0 = (const float4*)(s_seq + s0*SEQ_ST);
        const float4* a1 = (const float4*)(s_seq + (s0+100)*SEQ_ST);
        float acc0[Rc], acc1[Rc];
        #pragma unroll
        for (int r = 0; r < Rc; r++) { acc0[r] = 0.0f; acc1[r] = 0.0f; }
        #pragma unroll
        for (int d4 = 0; d4 < 16; d4++) {
            float4 x0 = a0[d4];
            float4 x1 = a1[d4];
            #pragma unroll
            for (int r = 0; r < Rc; r++) {
                float4 y = ((const float4*)(rib + r*SEQ_ST))[d4];   // broadcast, reused 2x
                acc0[r] = fmaf(x0.x, y.x, acc0[r]);
                acc0[r] = fmaf(x0.y, y.y, acc0[r]);
                acc0[r] = fmaf(x0.z, y.z, acc0[r]);
                acc0[r] = fmaf(x0.w, y.w, acc0[r]);
                acc1[r] = fmaf(x1.x, y.x, acc1[r]);
                acc1[r] = fmaf(x1.y, y.y, acc1[r]);
                acc1[r] = fmaf(x1.z, y.z, acc1[r]);
                acc1[r] = fmaf(x1.w, y.w, acc1[r]);
            }
        }
        float* w0 = s_att + (t*Sc + s0)*WST;
        float* w1 = s_att + (t*Sc + s0 + 100)*WST;
        ((float4*)w0)[0] = make_float4(acc0[0], acc0[1], acc0[2], acc0[3]);
        ((float4*)w0)[1] = make_float4(acc0[4], acc0[5], acc0[6], acc0[7]);
        ((float4*)w1)[0] = make_float4(acc1[0], acc1[1], acc1[2], acc1[3]);
        ((float4*)w1)[1] = make_float4(acc1[4], acc1[5], acc1[6], acc1[7]);
    } else {
        // decay: 112 threads cover 200 s in 2 rounds
        #pragma unroll
        for (int k = 0; k < 2; k++) {
            int s = (tid - 400) + k*112;
            if (s < Sc) {
                float dt = delta[b*Sc + s];
                int   v  = valid[b*Sc + s];
                s_val[s] = v ? 1.0f : 0.0f;
                float acc[Rc];
                #pragma unroll
                for (int r = 0; r < Rc; r++) acc[r] = 0.0f;
                #pragma unroll
                for (int f = 0; f < Fc; f++) {
                    float w = 3.14159265358979323846f * ((float)f * (1.0f/(Fc-1))) * dt;
                    float sn, cs;
                    __sincosf(w, &sn, &cs);
                    #pragma unroll
                    for (int r = 0; r < Rc; r++)
                        acc[r] = fmaf(cs, s_fr[r*Fc + f], fmaf(-sn, s_fi[r*Fc + f], acc[r]));
                }
                #pragma unroll
                for (int r = 0; r < Rc; r++) {
                    float d = acc[r] * (1.0f / (2.0f * Fc));
                    d = fminf(fmaxf(d, 0.0f), 1.0f);
                    if (!v) d = 0.0f;
                    s_dec[r*DEC_ST + s] = d;
                }
            }
        }
    }
    __syncthreads();

    // ---------------- softmax: warp (t,rg) handles 4 r-rows vectorized ----------------
    if (warp < 8) {
        const int t  = warp >> 1;
        const int rg = warp & 1;
        float* wbase = s_att + t*Sc*WST + rg*4;

        float4 av[7];
        float4 m4 = make_float4(-INFINITY, -INFINITY, -INFINITY, -INFINITY);
        #pragma unroll
        for (int i = 0; i < 7; i++) {
            int s = i*32 + lane;
            float4 a = make_float4(-INFINITY, -INFINITY, -INFINITY, -INFINITY);
            if (s < Sc && s_val[s] != 0.0f)
                a = *(const float4*)(wbase + s*WST);
            av[i] = a;
            m4.x = fmaxf(m4.x, a.x); m4.y = fmaxf(m4.y, a.y);
            m4.z = fmaxf(m4.z, a.z); m4.w = fmaxf(m4.w, a.w);
        }
        #pragma unroll
        for (int o = 16; o; o >>= 1) {
            m4.x = fmaxf(m4.x, __shfl_xor_sync(0xffffffffu, m4.x, o));
            m4.y = fmaxf(m4.y, __shfl_xor_sync(0xffffffffu, m4.y, o));
            m4.z = fmaxf(m4.z, __shfl_xor_sync(0xffffffffu, m4.z, o));
            m4.w = fmaxf(m4.w, __shfl_xor_sync(0xffffffffu, m4.w, o));
        }

        float4 sum4 = make_float4(0.f, 0.f, 0.f, 0.f);
        #pragma unroll
        for (int i = 0; i < 7; i++) {
            float4 e;
            e.x = __expf(av[i].x - m4.x);   // exp(-inf - m) = 0 for masked
            e.y = __expf(av[i].y - m4.y);
            e.z = __expf(av[i].z - m4.z);
            e.w = __expf(av[i].w - m4.w);
            av[i] = e;
            sum4.x += e.x; sum4.y += e.y; sum4.z += e.z; sum4.w += e.w;
        }
        #pragma unroll
        for (int o = 16; o; o >>= 1) {
            sum4.x += __shfl_xor_sync(0xffffffffu, sum4.x, o);
            sum4.y += __shfl_xor_sync(0xffffffffu, sum4.y, o);
            sum4.z += __shfl_xor_sync(0xffffffffu, sum4.z, o);
            sum4.w += __shfl_xor_sync(0xffffffffu, sum4.w, o);
        }
        float4 inv4 = make_float4(1.f/sum4.x, 1.f/sum4.y, 1.f/sum4.z, 1.f/sum4.w);

        #pragma unroll
        for (int i = 0; i < 7; i++) {
            int s = i*32 + lane;
            if (s < Sc) {
                float4 w;
                w.x = av[i].x * inv4.x * s_dec[(rg*4+0)*DEC_ST + s];
                w.y = av[i].y * inv4.y * s_dec[(rg*4+1)*DEC_ST + s];
                w.z = av[i].z * inv4.z * s_dec[(rg*4+2)*DEC_ST + s];
                w.w = av[i].w * inv4.w * s_dec[(rg*4+3)*DEC_ST + s];
                *(float4*)(wbase + s*WST) = w;
            }
        }
    }
    __syncthreads();

    // ---------------- context: warp=(t, chunk c of 4); 50 s, all 8 r; f32x2 accs ----------------
    const int ct = warp >> 2;
    const int cc = warp & 3;
    const int sh = lane >> 4;          // half-warp s-split
    const int dl = lane & 15;
    const int d0 = dl * 4;             // 4 d per lane (2 f32x2 pairs)
    u64 acc[16];                        // [r][pair]
    #pragma unroll
    for (int j = 0; j < 16; j++) acc[j] = 0ull;
    {
        const float* wb = s_att + ct*Sc*WST;
        const int sbase = cc * 50;
        #pragma unroll 5
        for (int it = 0; it < 25; it++) {
            int s = sbase + it*2 + sh;
            ulonglong2 q = *(const ulonglong2*)(s_seq + s*SEQ_ST + d0);
            const float4 w0 = *(const float4*)(wb + s*WST);      // r0..3 (half-warp bcast)
            const float4 w1 = *(const float4*)(wb + s*WST + 4);  // r4..7
            u64 wp;
            wp = pack2(w0.x, w0.x); acc[0]  = fma2(q.x, wp, acc[0]);  acc[1]  = fma2(q.y, wp, acc[1]);
            wp = pack2(w0.y, w0.y); acc[2]  = fma2(q.x, wp, acc[2]);  acc[3]  = fma2(q.y, wp, acc[3]);
            wp = pack2(w0.z, w0.z); acc[4]  = fma2(q.x, wp, acc[4]);  acc[5]  = fma2(q.y, wp, acc[5]);
            wp = pack2(w0.w, w0.w); acc[6]  = fma2(q.x, wp, acc[6]);  acc[7]  = fma2(q.y, wp, acc[7]);
            wp = pack2(w1.x, w1.x); acc[8]  = fma2(q.x, wp, acc[8]);  acc[9]  = fma2(q.y, wp, acc[9]);
            wp = pack2(w1.y, w1.y); acc[10] = fma2(q.x, wp, acc[10]); acc[11] = fma2(q.y, wp, acc[11]);
            wp = pack2(w1.z, w1.z); acc[12] = fma2(q.x, wp, acc[12]); acc[13] = fma2(q.y, wp, acc[13]);
            wp = pack2(w1.w, w1.w); acc[14] = fma2(q.x, wp, acc[14]); acc[15] = fma2(q.y, wp, acc[15]);
        }
        // combine the two s-halves
        #pragma unroll
        for (int j = 0; j < 16; j++)
            acc[j] = add2(acc[j], __shfl_xor_sync(0xffffffffu, acc[j], 16));
    }

    float* p1 = sm + OFF_P1;
    float* p2 = sm + OFF_P2;
    // stage A: chunks 1 and 3 publish (lanes 0..15 hold combined sums)
    if (lane < 16) {
        if (cc == 1) {
            ulonglong2* p = (ulonglong2*)(p1 + ct*512 + d0);
            #pragma unroll
            for (int r = 0; r < Rc; r++) { ulonglong2 v; v.x = acc[2*r]; v.y = acc[2*r+1]; p[r*16] = v; }
        } else if (cc == 3) {
            ulonglong2* p = (ulonglong2*)(p2 + ct*512 + d0);
            #pragma unroll
            for (int r = 0; r < Rc; r++) { ulonglong2 v; v.x = acc[2*r]; v.y = acc[2*r+1]; p[r*16] = v; }
        }
    }
    __syncthreads();
    if (lane < 16) {
        if (cc == 0) {
            const ulonglong2* p = (const ulonglong2*)(p1 + ct*512 + d0);
            #pragma unroll
            for (int r = 0; r < Rc; r++) { ulonglong2 v = p[r*16]; acc[2*r] = add2(acc[2*r], v.x); acc[2*r+1] = add2(acc[2*r+1], v.y); }
        } else if (cc == 2) {
            const ulonglong2* p = (const ulonglong2*)(p2 + ct*512 + d0);
            #pragma unroll
            for (int r = 0; r < Rc; r++) { ulonglong2 v = p[r*16]; acc[2*r] = add2(acc[2*r], v.x); acc[2*r+1] = add2(acc[2*r+1], v.y); }
        }
    }
    __syncthreads();
    // stage B: chunk 2 publishes into region 1
    if (lane < 16 && cc == 2) {
        ulonglong2* p = (ulonglong2*)(p1 + ct*512 + d0);
        #pragma unroll
        for (int r = 0; r < Rc; r++) { ulonglong2 v; v.x = acc[2*r]; v.y = acc[2*r+1]; p[r*16] = v; }
    }
    __syncthreads();
    if (lane < 16 && cc == 0) {
        const ulonglong2* p = (const ulonglong2*)(p1 + ct*512 + d0);
        #pragma unroll
        for (int r = 0; r < Rc; r++) {
            ulonglong2 v = p[r*16];
            ulonglong2 res;
            res.x = add2(acc[2*r], v.x);
            res.y = add2(acc[2*r+1], v.y);
            *(ulonglong2*)(out + (((size_t)(b*Tc + t0 + ct))*Rc + r)*Dc + d0) = res;
        }
    }
}

extern "C" void kernel_launch(void* const* d_in, const int* in_sizes, int n_in,
                              void* d_out, int out_size)
{
    const float* seq    = (const float*)d_in[0];
    const float* delta  = (const float*)d_in[1];
    const float* target = (const float*)d_in[2];
    const float* tv     = (const float*)d_in[3];
    const int*   valid  = (const int*)  d_in[4];
    const float* rel    = (const float*)d_in[5];
    const float* fr     = (const float*)d_in[6];
    const float* fi     = (const float*)d_in[7];
    float* out = (float*)d_out;

    cudaFuncSetAttribute(rda_kernel, cudaFuncAttributeMaxDynamicSharedMemorySize, SMEM_BYTES);
    dim3 grid(Tc/TPC, Bc);
    rda_kernel<<<grid, NT, SMEM_BYTES>>>(seq, delta, target, tv, valid, rel, fr, fi, out);
}